// round 5
// baseline (speedup 1.0000x reference)
#include <cuda_runtime.h>
#include <cuda_bf16.h>
#include <math.h>

// Problem constants
#define T_  16
#define DB_ 512
#define H_  512
#define U_  1024
#define MC_ 8
#define MT_ 4
#define L_  64
#define K_  64
#define Hh_ 256
#define G3_ (3*Hh_)     // 768
#define TU_ (T_*U_)     // 16384
#define TDB_ (T_*DB_)   // 8192
#define OUTC_ (U_+K_)   // 1088

// ---------------- scratch (device globals; no allocs allowed) ----------------
__device__ float d_Pf[TDB_*G3_];      // feat @ Wih_f^T   (8192 x 768)
__device__ float d_Pb[TDB_*G3_];      // feat @ Wih_b^T
__device__ float d_g_f1[TU_*G3_];     // tab-mean of Pf  (gi for f1, no bias)
__device__ float d_g_b2[TU_*G3_];     // tab-mean of Pb  (gi for b2)
__device__ float d_g_f2[TU_*G3_];     // col-mean of Pf  (gi for f2)
__device__ float d_g_b1[TU_*G3_];     // col-mean of Pb  (gi for b1)
__device__ float d_f1[TU_*Hh_];
__device__ float d_b1[TU_*Hh_];
__device__ float d_gh_f[TU_*G3_];     // f1@Whh_f^T + bhh_f
__device__ float d_gh_b[TU_*G3_];     // b1@Whh_b^T + bhh_b
__device__ float d_db[TU_*H_];        // db_emb
__device__ float d_logits[T_*U_];
__device__ float d_wsm[T_*U_];
__device__ float d_attnv[T_*H_];
__device__ float d_ffin[T_*L_*H_];
__device__ float d_ff[T_*L_*H_];
__device__ float d_probs[T_*L_*OUTC_];

// packed f32x2 FMA: acc = a*b + acc (elementwise on 2-float packs)
__device__ __forceinline__ void ffma2(unsigned long long& acc,
                                      unsigned long long a, unsigned long long b)
{
    asm("fma.rn.f32x2 %0, %1, %2, %0;" : "+l"(acc) : "l"(a), "l"(b));
}

// ---------------- tiled SGEMM with packed-f32x2 core ----------------
// C = A(MxK) * B(NxK)^T + bias, opt tanh. 2x2 microblocks via FFMA2:
//   accd holds (C[i][j], C[i+1][j+1]) ; accs holds (C[i][j+1], C[i+1][j])
//   computed from a-pair (a_i, a_{i+1}) against natural and pair-swapped b pairs.
template<int BM, int BN, int BK, int TM, int TN>
__global__ void sgemm_nt(const float* __restrict__ A, const float* __restrict__ B,
                         const float* __restrict__ bias, float* __restrict__ C,
                         int M, int N, int K, int lda, int ldb, int ldc,
                         long long sA, long long sB, long long sC, int act)
{
    constexpr int THREADS = (BM/TM) * (BN/TN);
    __shared__ float As [BK][BM];
    __shared__ float Bs [BK][BN];   // natural order
    __shared__ float BsS[BK][BN];   // pair-swapped: BsS[k][n] = Bs[k][n^1]

    A += (size_t)blockIdx.z * sA;
    B += (size_t)blockIdx.z * sB;
    C += (size_t)blockIdx.z * sC;

    int bm = blockIdx.y * BM;
    int bn = blockIdx.x * BN;
    int tid = threadIdx.x;
    int tx = tid % (BN/TN);
    int ty = tid / (BN/TN);

    unsigned long long accd[TM/2][TN/2];
    unsigned long long accs[TM/2][TN/2];
    #pragma unroll
    for (int i = 0; i < TM/2; i++)
        #pragma unroll
        for (int j = 0; j < TN/2; j++) { accd[i][j] = 0ull; accs[i][j] = 0ull; }

    for (int k0 = 0; k0 < K; k0 += BK) {
        #pragma unroll
        for (int i = tid; i < BM*BK/4; i += THREADS) {
            int r = i / (BK/4), c4 = i % (BK/4);
            float4 v = *(const float4*)&A[(size_t)(bm+r)*lda + k0 + c4*4];
            As[c4*4+0][r] = v.x; As[c4*4+1][r] = v.y;
            As[c4*4+2][r] = v.z; As[c4*4+3][r] = v.w;
        }
        #pragma unroll
        for (int i = tid; i < BN*BK/4; i += THREADS) {
            int r = i / (BK/4), c4 = i % (BK/4);
            float4 v = *(const float4*)&B[(size_t)(bn+r)*ldb + k0 + c4*4];
            Bs [c4*4+0][r]   = v.x; Bs [c4*4+1][r]   = v.y;
            Bs [c4*4+2][r]   = v.z; Bs [c4*4+3][r]   = v.w;
            int rs = r ^ 1;
            BsS[c4*4+0][rs]  = v.x; BsS[c4*4+1][rs]  = v.y;
            BsS[c4*4+2][rs]  = v.z; BsS[c4*4+3][rs]  = v.w;
        }
        __syncthreads();
        #pragma unroll
        for (int kk = 0; kk < BK; kk++) {
            unsigned long long a2[TM/2], bn2[TN/2], bs2[TN/2];
            #pragma unroll
            for (int i = 0; i < TM/2; i++)
                a2[i] = *(const unsigned long long*)&As[kk][ty*TM + 2*i];
            #pragma unroll
            for (int j = 0; j < TN/2; j++) {
                bn2[j] = *(const unsigned long long*)&Bs [kk][tx*TN + 2*j];
                bs2[j] = *(const unsigned long long*)&BsS[kk][tx*TN + 2*j];
            }
            #pragma unroll
            for (int i = 0; i < TM/2; i++)
                #pragma unroll
                for (int j = 0; j < TN/2; j++) {
                    ffma2(accd[i][j], a2[i], bn2[j]);
                    ffma2(accs[i][j], a2[i], bs2[j]);
                }
        }
        __syncthreads();
    }

    // unpack 2x2 microblocks and store
    #pragma unroll
    for (int i2 = 0; i2 < TM/2; i2++) {
        #pragma unroll
        for (int j2 = 0; j2 < TN/2; j2++) {
            float2 dv = *(float2*)&accd[i2][j2];
            float2 sv = *(float2*)&accs[i2][j2];
            int m0 = bm + ty*TM + 2*i2;
            int n0 = bn + tx*TN + 2*j2;
            float c00 = dv.x, c11 = dv.y, c01 = sv.x, c10 = sv.y;
            if (bias) {
                float b0 = bias[n0], b1v = bias[n0+1];
                c00 += b0; c10 += b0; c01 += b1v; c11 += b1v;
            }
            if (act == 1) { c00 = tanhf(c00); c01 = tanhf(c01); c10 = tanhf(c10); c11 = tanhf(c11); }
            C[(size_t)m0*ldc + n0]       = c00;
            C[(size_t)m0*ldc + n0+1]     = c01;
            C[(size_t)(m0+1)*ldc + n0]   = c10;
            C[(size_t)(m0+1)*ldc + n0+1] = c11;
        }
    }
}

// ---------------- masked mean gather IN PROJECTED SPACE ----------------
__global__ void proj_gather_kernel(const int* __restrict__ col_idx, const int* __restrict__ col_mask,
                                   const int* __restrict__ tab_idx, const int* __restrict__ tab_mask)
{
    int u = blockIdx.x, t = blockIdx.y;
    int h4 = threadIdx.x;               // 192 threads, float4 each -> 768 floats
    const float* Pf = d_Pf + (size_t)t * DB_ * G3_;
    const float* Pb = d_Pb + (size_t)t * DB_ * G3_;
    size_t orow = ((size_t)t*U_ + u) * G3_ + h4*4;

    // tab (x1) -> g_f1 (Pf), g_b2 (Pb)
    {
        float4 af = make_float4(0.f,0.f,0.f,0.f);
        float4 ab = make_float4(0.f,0.f,0.f,0.f);
        float cnt = 0.f;
        #pragma unroll
        for (int m = 0; m < MT_; m++) {
            if (tab_mask[u*MT_+m]) {
                int id = tab_idx[u*MT_+m];
                float4 vf = *(const float4*)&Pf[(size_t)id*G3_ + h4*4];
                float4 vb = *(const float4*)&Pb[(size_t)id*G3_ + h4*4];
                af.x += vf.x; af.y += vf.y; af.z += vf.z; af.w += vf.w;
                ab.x += vb.x; ab.y += vb.y; ab.z += vb.z; ab.w += vb.w;
                cnt += 1.f;
            }
        }
        float inv = 1.f / fmaxf(cnt, 1.f);
        af.x *= inv; af.y *= inv; af.z *= inv; af.w *= inv;
        ab.x *= inv; ab.y *= inv; ab.z *= inv; ab.w *= inv;
        *(float4*)&d_g_f1[orow] = af;
        *(float4*)&d_g_b2[orow] = ab;
    }
    // col (x2) -> g_f2 (Pf), g_b1 (Pb)
    {
        float4 af = make_float4(0.f,0.f,0.f,0.f);
        float4 ab = make_float4(0.f,0.f,0.f,0.f);
        float cnt = 0.f;
        #pragma unroll
        for (int m = 0; m < MC_; m++) {
            if (col_mask[u*MC_+m]) {
                int id = col_idx[u*MC_+m];
                float4 vf = *(const float4*)&Pf[(size_t)id*G3_ + h4*4];
                float4 vb = *(const float4*)&Pb[(size_t)id*G3_ + h4*4];
                af.x += vf.x; af.y += vf.y; af.z += vf.z; af.w += vf.w;
                ab.x += vb.x; ab.y += vb.y; ab.z += vb.z; ab.w += vb.w;
                cnt += 1.f;
            }
        }
        float inv = 1.f / fmaxf(cnt, 1.f);
        af.x *= inv; af.y *= inv; af.z *= inv; af.w *= inv;
        ab.x *= inv; ab.y *= inv; ab.z *= inv; ab.w *= inv;
        *(float4*)&d_g_f2[orow] = af;
        *(float4*)&d_g_b1[orow] = ab;
    }
}

// ---------------- GRU elementwise ----------------
__device__ __forceinline__ float sigm(float x) { return 1.f / (1.f + expf(-x)); }

__global__ void gru_first_kernel(const float* __restrict__ bih_f, const float* __restrict__ bhh_f,
                                 const float* __restrict__ bih_b, const float* __restrict__ bhh_b)
{
    int idx = blockIdx.x * blockDim.x + threadIdx.x;   // TU_*Hh_
    int row = idx >> 8, j = idx & 255;
    {
        const float* g = d_g_f1 + (size_t)row * G3_;
        float r = sigm(g[j]       + bih_f[j]       + bhh_f[j]);
        float z = sigm(g[Hh_+j]   + bih_f[Hh_+j]   + bhh_f[Hh_+j]);
        float n = tanhf(g[2*Hh_+j] + bih_f[2*Hh_+j] + r * bhh_f[2*Hh_+j]);
        d_f1[idx] = (1.f - z) * n;
    }
    {
        const float* g = d_g_b1 + (size_t)row * G3_;
        float r = sigm(g[j]       + bih_b[j]       + bhh_b[j]);
        float z = sigm(g[Hh_+j]   + bih_b[Hh_+j]   + bhh_b[Hh_+j]);
        float n = tanhf(g[2*Hh_+j] + bih_b[2*Hh_+j] + r * bhh_b[2*Hh_+j]);
        d_b1[idx] = (1.f - z) * n;
    }
}

__global__ void gru_second_kernel(const float* __restrict__ bih_f, const float* __restrict__ bih_b)
{
    int idx = blockIdx.x * blockDim.x + threadIdx.x;   // TU_*Hh_
    int row = idx >> 8, j = idx & 255;
    // forward step 2: x2, h=f1
    {
        const float* gi = d_g_f2 + (size_t)row * G3_;
        const float* gh = d_gh_f + (size_t)row * G3_;
        float h  = d_f1[idx];
        float r = sigm(gi[j]       + bih_f[j]       + gh[j]);
        float z = sigm(gi[Hh_+j]   + bih_f[Hh_+j]   + gh[Hh_+j]);
        float n = tanhf(gi[2*Hh_+j] + bih_f[2*Hh_+j] + r * gh[2*Hh_+j]);
        float f2 = (1.f - z) * n + z * h;
        d_db[(size_t)row*H_ + j] = 0.5f * (h + f2);
    }
    // backward step 2: x1, h=b1
    {
        const float* gi = d_g_b2 + (size_t)row * G3_;
        const float* gh = d_gh_b + (size_t)row * G3_;
        float h  = d_b1[idx];
        float r = sigm(gi[j]       + bih_b[j]       + gh[j]);
        float z = sigm(gi[Hh_+j]   + bih_b[Hh_+j]   + gh[Hh_+j]);
        float n = tanhf(gi[2*Hh_+j] + bih_b[2*Hh_+j] + r * gh[2*Hh_+j]);
        float b2 = (1.f - z) * n + z * h;
        d_db[(size_t)row*H_ + Hh_ + j] = 0.5f * (h + b2);
    }
}

// ---------------- attention ----------------
__global__ void logits_kernel(const float* __restrict__ key, const int* __restrict__ attn_mask)
{
    int t = blockIdx.y;
    int warp = threadIdx.x >> 5, lane = threadIdx.x & 31;
    int u = blockIdx.x * 8 + warp;
    const float* kv = key + (size_t)t * H_;
    const float* d  = d_db + ((size_t)t*U_ + u) * H_;
    float acc = 0.f;
    for (int h = lane; h < H_; h += 32) acc += kv[h] * d[h];
    #pragma unroll
    for (int s = 16; s > 0; s >>= 1) acc += __shfl_xor_sync(0xFFFFFFFFu, acc, s);
    if (lane == 0)
        d_logits[t*U_ + u] = attn_mask[t*U_ + u] ? acc : -1e9f;
}

__global__ void softmax_kernel()
{
    int t = blockIdx.x;
    __shared__ float red[256];
    int tid = threadIdx.x;
    float mx = -INFINITY;
    for (int u = tid; u < U_; u += 256) mx = fmaxf(mx, d_logits[t*U_+u]);
    red[tid] = mx; __syncthreads();
    for (int s = 128; s > 0; s >>= 1) { if (tid < s) red[tid] = fmaxf(red[tid], red[tid+s]); __syncthreads(); }
    mx = red[0]; __syncthreads();
    float sum = 0.f;
    for (int u = tid; u < U_; u += 256) sum += expf(d_logits[t*U_+u] - mx);
    red[tid] = sum; __syncthreads();
    for (int s = 128; s > 0; s >>= 1) { if (tid < s) red[tid] += red[tid+s]; __syncthreads(); }
    sum = red[0];
    float inv = 1.f / sum;
    for (int u = tid; u < U_; u += 256) d_wsm[t*U_+u] = expf(d_logits[t*U_+u] - mx) * inv;
}

__global__ void attn_kernel()
{
    int t = blockIdx.x;
    int h = threadIdx.x;                 // 512 threads
    __shared__ float ws[U_];
    for (int u = h; u < U_; u += H_) ws[u] = d_wsm[t*U_+u];
    __syncthreads();
    float acc = 0.f;
    const float* d = d_db + (size_t)t*U_*H_ + h;
    for (int u = 0; u < U_; u++) acc += ws[u] * d[(size_t)u*H_];
    d_attnv[t*H_ + h] = acc;
}

__global__ void add_attn_kernel(const float* __restrict__ final_feature)
{
    int idx = blockIdx.x * blockDim.x + threadIdx.x;   // T_*L_*H_
    int h = idx & (H_-1);
    int t = idx >> 15;                                 // / (L_*H_)
    d_ffin[idx] = final_feature[idx] + d_attnv[t*H_ + h];
}

// ---------------- final log-softmax ----------------
__global__ void logsoftmax_kernel(float* __restrict__ out)
{
    int r = blockIdx.x;                 // T_*L_ rows
    int tid = threadIdx.x;
    __shared__ float red[256];
    const float* x = d_probs + (size_t)r * OUTC_;
    float mx = -INFINITY;
    for (int c = tid; c < OUTC_; c += 256) mx = fmaxf(mx, x[c]);
    red[tid] = mx; __syncthreads();
    for (int s = 128; s > 0; s >>= 1) { if (tid < s) red[tid] = fmaxf(red[tid], red[tid+s]); __syncthreads(); }
    mx = red[0]; __syncthreads();
    float sum = 0.f;
    for (int c = tid; c < OUTC_; c += 256) sum += expf(x[c] - mx);
    red[tid] = sum; __syncthreads();
    for (int s = 128; s > 0; s >>= 1) { if (tid < s) red[tid] += red[tid+s]; __syncthreads(); }
    float lse = mx + logf(red[0]);
    for (int c = tid; c < OUTC_; c += 256) out[(size_t)r*OUTC_ + c] = x[c] - lse;
}

// ---------------- host launcher ----------------
#define SYM(p, s) do { void* _t; cudaGetSymbolAddress(&_t, s); (p) = (float*)_t; } while (0)

extern "C" void kernel_launch(void* const* d_in, const int* in_sizes, int n_in,
                              void* d_out, int out_size)
{
    const float* feat          = (const float*)d_in[0];
    const float* key           = (const float*)d_in[1];
    const float* final_feature = (const float*)d_in[2];
    const float* Wih_f         = (const float*)d_in[3];
    const float* Whh_f         = (const float*)d_in[4];
    const float* bih_f         = (const float*)d_in[5];
    const float* bhh_f         = (const float*)d_in[6];
    const float* Wih_b         = (const float*)d_in[7];
    const float* Whh_b         = (const float*)d_in[8];
    const float* bih_b         = (const float*)d_in[9];
    const float* bhh_b         = (const float*)d_in[10];
    const float* Wb            = (const float*)d_in[11];
    const float* bb            = (const float*)d_in[12];
    const float* Kemb          = (const float*)d_in[13];
    const int*   col_idx       = (const int*)d_in[14];
    const int*   col_mask      = (const int*)d_in[15];
    const int*   tab_idx       = (const int*)d_in[16];
    const int*   tab_mask      = (const int*)d_in[17];
    const int*   attn_mask     = (const int*)d_in[18];
    float* out = (float*)d_out;

    float *Pf, *Pb, *f1, *b1, *gh_f, *gh_b, *db, *ffin, *ff, *probs;
    SYM(Pf, d_Pf);   SYM(Pb, d_Pb);
    SYM(f1, d_f1);   SYM(b1, d_b1);
    SYM(gh_f, d_gh_f); SYM(gh_b, d_gh_b);
    SYM(db, d_db);   SYM(ffin, d_ffin); SYM(ff, d_ff); SYM(probs, d_probs);

    // 1) project ALL feat rows once: P = feat(8192x512) @ Wih^T  (768 wide each)
    {
        dim3 grid(G3_/128, TDB_/128, 1);
        sgemm_nt<128,128,16,8,8><<<grid, 256>>>(feat, Wih_f, nullptr, Pf, TDB_, G3_, H_, H_, H_, G3_, 0,0,0, 0);
        sgemm_nt<128,128,16,8,8><<<grid, 256>>>(feat, Wih_b, nullptr, Pb, TDB_, G3_, H_, H_, H_, G3_, 0,0,0, 0);
    }

    // 2) masked means in projected space -> gi buffers
    proj_gather_kernel<<<dim3(U_, T_), 192>>>(col_idx, col_mask, tab_idx, tab_mask);

    // 3) first GRU steps (h = 0)
    gru_first_kernel<<<TU_*Hh_/256, 256>>>(bih_f, bhh_f, bih_b, bhh_b);

    // 4) hidden-projection GEMMs: (16384 x 768) = (16384 x 256) @ (768 x 256)^T  (+bhh)
    {
        dim3 grid(G3_/128, TU_/128, 1);
        sgemm_nt<128,128,16,8,8><<<grid, 256>>>(f1, Whh_f, bhh_f, gh_f, TU_, G3_, Hh_, Hh_, Hh_, G3_, 0,0,0, 0);
        sgemm_nt<128,128,16,8,8><<<grid, 256>>>(b1, Whh_b, bhh_b, gh_b, TU_, G3_, Hh_, Hh_, Hh_, G3_, 0,0,0, 0);
    }

    // 5) second GRU steps + db_emb
    gru_second_kernel<<<TU_*Hh_/256, 256>>>(bih_f, bih_b);

    // 6) attention
    logits_kernel<<<dim3(U_/8, T_), 256>>>(key, attn_mask);
    softmax_kernel<<<T_, 256>>>();
    attn_kernel<<<T_, H_>>>();

    // 7) feature + attn, then ff = tanh(ffin @ Wb^T + bb)
    add_attn_kernel<<<T_*L_*H_/256, 256>>>(final_feature);
    {
        dim3 grid(H_/128, T_*L_/128, 1);
        sgemm_nt<128,128,16,8,8><<<grid, 256>>>(ffin, Wb, bb, ff, T_*L_, H_, H_, H_, H_, H_, 0,0,0, 1);
    }

    // 8) db_prob: per-t (64 x 1024) = ff[t] (64x512) @ db_emb[t] (1024x512)^T
    {
        dim3 grid(U_/128, L_/64, T_);
        sgemm_nt<64,128,16,4,8><<<grid, 256>>>(ff, db, nullptr, probs,
            L_, U_, H_, H_, H_, OUTC_,
            (long long)L_*H_, (long long)U_*H_, (long long)L_*OUTC_, 0);
    }
    // 9) kw_prob: (1024 x 64) = ff @ Kemb^T, at column offset U_
    {
        dim3 grid(K_/64, T_*L_/64, 1);
        sgemm_nt<64,64,16,4,4><<<grid, 256>>>(ff, Kemb, nullptr, probs + U_,
            T_*L_, K_, H_, H_, H_, OUTC_, 0,0,0, 0);
    }

    // 10) log-softmax over last dim (1088) -> output
    logsoftmax_kernel<<<T_*L_, 256>>>(out);
}

// round 7
// speedup vs baseline: 1.9428x; 1.9428x over previous
#include <cuda_runtime.h>
#include <cuda_bf16.h>
#include <mma.h>
#include <math.h>
#include <stdint.h>

using namespace nvcuda;

// Problem constants
#define T_  16
#define DB_ 512
#define H_  512
#define U_  1024
#define MC_ 8
#define MT_ 4
#define L_  64
#define K_  64
#define Hh_ 256
#define G3_ (3*Hh_)     // 768
#define TU_ (T_*U_)     // 16384
#define TDB_ (T_*DB_)   // 8192
#define OUTC_ (U_+K_)   // 1088

// ---------------- scratch (device globals; no allocs allowed) ----------------
__device__ float d_Pf[TDB_*G3_];      // feat @ Wih_f^T   (8192 x 768)
__device__ float d_Pb[TDB_*G3_];      // feat @ Wih_b^T
__device__ float d_g_f1[TU_*G3_];
__device__ float d_g_b2[TU_*G3_];
__device__ float d_g_f2[TU_*G3_];
__device__ float d_g_b1[TU_*G3_];
__device__ float d_f1[TU_*Hh_];
__device__ float d_b1[TU_*Hh_];
__device__ float d_gh_f[TU_*G3_];     // f1@Whh_f^T  (NO bias; bhh added in gru_second)
__device__ float d_gh_b[TU_*G3_];
__device__ float d_db[TU_*H_];        // db_emb
__device__ float d_logits[T_*U_];
__device__ float d_wsm[T_*U_];
__device__ float d_attnv[T_*H_];
__device__ float d_ffin[T_*L_*H_];
__device__ float d_ff[T_*L_*H_];
__device__ float d_probs[T_*L_*OUTC_];

// split-bf16 operand buffers ([hi|lo|hi] for A-side, [hi|hi|lo] for B-side)
__device__ __nv_bfloat16 d_featS[TDB_*3*H_];   // 8192 x 1536
__device__ __nv_bfloat16 d_WihfS[G3_*3*H_];    // 768 x 1536
__device__ __nv_bfloat16 d_WihbS[G3_*3*H_];
__device__ __nv_bfloat16 d_WhhfS[G3_*3*Hh_];   // 768 x 768
__device__ __nv_bfloat16 d_WhhbS[G3_*3*Hh_];
__device__ __nv_bfloat16 d_f1S[TU_*3*Hh_];     // 16384 x 768
__device__ __nv_bfloat16 d_b1S[TU_*3*Hh_];

// ================= WMMA bf16 GEMM (HMMA path, arch-agnostic) =================
// C(MxN) = A(M x K3) @ B(N x K3)^T ; bf16 operands, fp32 accumulate.
// Tile: BM=128, BN=128, BK=32; 256 threads = 8 warps (2x4), warp tile 64x32.
#define WBK 32
#define WPAD 48   // smem leading dim (elements): 96B rows (32B-aligned, %8==0)

__global__ __launch_bounds__(256)
void gemm_wmma(const __nv_bfloat16* __restrict__ A, const __nv_bfloat16* __restrict__ B,
               float* __restrict__ C, int M, int N, int K3, int ldc)
{
    __shared__ __nv_bfloat16 As[128 * WPAD];
    __shared__ __nv_bfloat16 Bs[128 * WPAD];

    int tid  = threadIdx.x;
    int warp = tid >> 5;
    int wm = warp >> 2;          // 0..1 : 64-row slab
    int wn = warp & 3;           // 0..3 : 32-col slab
    int bm = blockIdx.y * 128;
    int bn = blockIdx.x * 128;

    wmma::fragment<wmma::accumulator, 16, 16, 16, float> acc[4][2];
    #pragma unroll
    for (int i = 0; i < 4; i++)
        #pragma unroll
        for (int j = 0; j < 2; j++) wmma::fill_fragment(acc[i][j], 0.0f);

    for (int k0 = 0; k0 < K3; k0 += WBK) {
        // stage A tile (128 x 32) and B tile (128 x 32), 8 bf16 per thread per array
        #pragma unroll
        for (int i = tid; i < 128 * (WBK/8); i += 256) {
            int r = i >> 2, c = i & 3;
            *(uint4*)&As[r * WPAD + c * 8] = *(const uint4*)(A + (size_t)(bm + r) * K3 + k0 + c * 8);
        }
        #pragma unroll
        for (int i = tid; i < 128 * (WBK/8); i += 256) {
            int r = i >> 2, c = i & 3;
            *(uint4*)&Bs[r * WPAD + c * 8] = *(const uint4*)(B + (size_t)(bn + r) * K3 + k0 + c * 8);
        }
        __syncthreads();

        #pragma unroll
        for (int kk = 0; kk < WBK; kk += 16) {
            wmma::fragment<wmma::matrix_a, 16, 16, 16, __nv_bfloat16, wmma::row_major> fa[4];
            wmma::fragment<wmma::matrix_b, 16, 16, 16, __nv_bfloat16, wmma::col_major> fb[2];
            #pragma unroll
            for (int i = 0; i < 4; i++)
                wmma::load_matrix_sync(fa[i], &As[(wm * 64 + i * 16) * WPAD + kk], WPAD);
            #pragma unroll
            for (int j = 0; j < 2; j++)
                wmma::load_matrix_sync(fb[j], &Bs[(wn * 32 + j * 16) * WPAD + kk], WPAD);
            #pragma unroll
            for (int i = 0; i < 4; i++)
                #pragma unroll
                for (int j = 0; j < 2; j++)
                    wmma::mma_sync(acc[i][j], fa[i], fb[j], acc[i][j]);
        }
        __syncthreads();
    }

    #pragma unroll
    for (int i = 0; i < 4; i++)
        #pragma unroll
        for (int j = 0; j < 2; j++) {
            int m0 = bm + wm * 64 + i * 16;
            int n0 = bn + wn * 32 + j * 16;
            wmma::store_matrix_sync(C + (size_t)m0 * ldc + n0, acc[i][j], ldc, wmma::mem_row_major);
        }
}

// ================= split-bf16 conversion =================
// orderB=0: [hi|lo|hi] (A-side) ; orderB=1: [hi|hi|lo] (B-side)
__global__ void split_bf16_kernel(const float* __restrict__ X, __nv_bfloat16* __restrict__ Y,
                                  int n, int Kd, int orderB)
{
    int idx = blockIdx.x * blockDim.x + threadIdx.x;
    if (idx >= n) return;
    float x = X[idx];
    __nv_bfloat16 h = __float2bfloat16(x);
    __nv_bfloat16 l = __float2bfloat16(x - __bfloat162float(h));
    int r = idx / Kd, k = idx - r * Kd;
    size_t bse = (size_t)r * 3 * Kd;
    if (orderB) { Y[bse + k] = h; Y[bse + Kd + k] = h; Y[bse + 2*Kd + k] = l; }
    else        { Y[bse + k] = h; Y[bse + Kd + k] = l; Y[bse + 2*Kd + k] = h; }
}

// ---------------- scalar-FFMA SGEMM (small tail GEMMs) ----------------
template<int BM, int BN, int BK, int TM, int TN>
__global__ void sgemm_nt(const float* __restrict__ A, const float* __restrict__ B,
                         const float* __restrict__ bias, float* __restrict__ C,
                         int M, int N, int K, int lda, int ldb, int ldc,
                         long long sA, long long sB, long long sC, int act)
{
    constexpr int THREADS = (BM/TM) * (BN/TN);
    __shared__ float As[BK][BM];
    __shared__ float Bs[BK][BN];

    A += (size_t)blockIdx.z * sA;
    B += (size_t)blockIdx.z * sB;
    C += (size_t)blockIdx.z * sC;

    int bm = blockIdx.y * BM;
    int bn = blockIdx.x * BN;
    int tid = threadIdx.x;
    int tx = tid % (BN/TN);
    int ty = tid / (BN/TN);

    float acc[TM][TN];
    #pragma unroll
    for (int i = 0; i < TM; i++)
        #pragma unroll
        for (int j = 0; j < TN; j++) acc[i][j] = 0.f;

    for (int k0 = 0; k0 < K; k0 += BK) {
        #pragma unroll
        for (int i = tid; i < BM*BK/4; i += THREADS) {
            int r = i / (BK/4), c4 = i % (BK/4);
            float4 v = *(const float4*)&A[(size_t)(bm+r)*lda + k0 + c4*4];
            As[c4*4+0][r] = v.x; As[c4*4+1][r] = v.y;
            As[c4*4+2][r] = v.z; As[c4*4+3][r] = v.w;
        }
        #pragma unroll
        for (int i = tid; i < BN*BK/4; i += THREADS) {
            int r = i / (BK/4), c4 = i % (BK/4);
            float4 v = *(const float4*)&B[(size_t)(bn+r)*ldb + k0 + c4*4];
            Bs[c4*4+0][r] = v.x; Bs[c4*4+1][r] = v.y;
            Bs[c4*4+2][r] = v.z; Bs[c4*4+3][r] = v.w;
        }
        __syncthreads();
        #pragma unroll
        for (int kk = 0; kk < BK; kk++) {
            float a[TM], b[TN];
            #pragma unroll
            for (int i = 0; i < TM; i++) a[i] = As[kk][ty*TM + i];
            #pragma unroll
            for (int j = 0; j < TN; j++) b[j] = Bs[kk][tx*TN + j];
            #pragma unroll
            for (int i = 0; i < TM; i++)
                #pragma unroll
                for (int j = 0; j < TN; j++) acc[i][j] += a[i]*b[j];
        }
        __syncthreads();
    }

    #pragma unroll
    for (int i = 0; i < TM; i++) {
        int m = bm + ty*TM + i;
        #pragma unroll
        for (int j = 0; j < TN; j++) {
            int n = bn + tx*TN + j;
            float v = acc[i][j];
            if (bias) v += bias[n];
            if (act == 1) v = tanhf(v);
            C[(size_t)m*ldc + n] = v;
        }
    }
}

// ---------------- masked mean gather IN PROJECTED SPACE ----------------
__global__ void proj_gather_kernel(const int* __restrict__ col_idx, const int* __restrict__ col_mask,
                                   const int* __restrict__ tab_idx, const int* __restrict__ tab_mask)
{
    int u = blockIdx.x, t = blockIdx.y;
    int h4 = threadIdx.x;               // 192 threads, float4 each -> 768 floats
    const float* Pf = d_Pf + (size_t)t * DB_ * G3_;
    const float* Pb = d_Pb + (size_t)t * DB_ * G3_;
    size_t orow = ((size_t)t*U_ + u) * G3_ + h4*4;

    {
        float4 af = make_float4(0.f,0.f,0.f,0.f);
        float4 ab = make_float4(0.f,0.f,0.f,0.f);
        float cnt = 0.f;
        #pragma unroll
        for (int m = 0; m < MT_; m++) {
            if (tab_mask[u*MT_+m]) {
                int id = tab_idx[u*MT_+m];
                float4 vf = *(const float4*)&Pf[(size_t)id*G3_ + h4*4];
                float4 vb = *(const float4*)&Pb[(size_t)id*G3_ + h4*4];
                af.x += vf.x; af.y += vf.y; af.z += vf.z; af.w += vf.w;
                ab.x += vb.x; ab.y += vb.y; ab.z += vb.z; ab.w += vb.w;
                cnt += 1.f;
            }
        }
        float inv = 1.f / fmaxf(cnt, 1.f);
        af.x *= inv; af.y *= inv; af.z *= inv; af.w *= inv;
        ab.x *= inv; ab.y *= inv; ab.z *= inv; ab.w *= inv;
        *(float4*)&d_g_f1[orow] = af;
        *(float4*)&d_g_b2[orow] = ab;
    }
    {
        float4 af = make_float4(0.f,0.f,0.f,0.f);
        float4 ab = make_float4(0.f,0.f,0.f,0.f);
        float cnt = 0.f;
        #pragma unroll
        for (int m = 0; m < MC_; m++) {
            if (col_mask[u*MC_+m]) {
                int id = col_idx[u*MC_+m];
                float4 vf = *(const float4*)&Pf[(size_t)id*G3_ + h4*4];
                float4 vb = *(const float4*)&Pb[(size_t)id*G3_ + h4*4];
                af.x += vf.x; af.y += vf.y; af.z += vf.z; af.w += vf.w;
                ab.x += vb.x; ab.y += vb.y; ab.z += vb.z; ab.w += vb.w;
                cnt += 1.f;
            }
        }
        float inv = 1.f / fmaxf(cnt, 1.f);
        af.x *= inv; af.y *= inv; af.z *= inv; af.w *= inv;
        ab.x *= inv; ab.y *= inv; ab.z *= inv; ab.w *= inv;
        *(float4*)&d_g_f2[orow] = af;
        *(float4*)&d_g_b1[orow] = ab;
    }
}

// ---------------- GRU elementwise ----------------
__device__ __forceinline__ float sigm(float x) { return 1.f / (1.f + expf(-x)); }

// first steps (h=0). Also emits f1/b1 in split-bf16 [hi|lo|hi].
__global__ void gru_first_kernel(const float* __restrict__ bih_f, const float* __restrict__ bhh_f,
                                 const float* __restrict__ bih_b, const float* __restrict__ bhh_b)
{
    int idx = blockIdx.x * blockDim.x + threadIdx.x;   // TU_*Hh_
    int row = idx >> 8, j = idx & 255;
    size_t sb = (size_t)row * G3_;
    {
        const float* g = d_g_f1 + sb;
        float r = sigm(g[j]       + bih_f[j]       + bhh_f[j]);
        float z = sigm(g[Hh_+j]   + bih_f[Hh_+j]   + bhh_f[Hh_+j]);
        float n = tanhf(g[2*Hh_+j] + bih_f[2*Hh_+j] + r * bhh_f[2*Hh_+j]);
        float v = (1.f - z) * n;
        d_f1[idx] = v;
        __nv_bfloat16 h = __float2bfloat16(v);
        __nv_bfloat16 l = __float2bfloat16(v - __bfloat162float(h));
        d_f1S[sb + j] = h; d_f1S[sb + Hh_ + j] = l; d_f1S[sb + 2*Hh_ + j] = h;
    }
    {
        const float* g = d_g_b1 + sb;
        float r = sigm(g[j]       + bih_b[j]       + bhh_b[j]);
        float z = sigm(g[Hh_+j]   + bih_b[Hh_+j]   + bhh_b[Hh_+j]);
        float n = tanhf(g[2*Hh_+j] + bih_b[2*Hh_+j] + r * bhh_b[2*Hh_+j]);
        float v = (1.f - z) * n;
        d_b1[idx] = v;
        __nv_bfloat16 h = __float2bfloat16(v);
        __nv_bfloat16 l = __float2bfloat16(v - __bfloat162float(h));
        d_b1S[sb + j] = h; d_b1S[sb + Hh_ + j] = l; d_b1S[sb + 2*Hh_ + j] = h;
    }
}

// second steps: gh buffers are RAW h@Whh^T (no bias) -> add bhh here; gi needs +bih.
__global__ void gru_second_kernel(const float* __restrict__ bih_f, const float* __restrict__ bhh_f,
                                  const float* __restrict__ bih_b, const float* __restrict__ bhh_b)
{
    int idx = blockIdx.x * blockDim.x + threadIdx.x;   // TU_*Hh_
    int row = idx >> 8, j = idx & 255;
    {
        const float* gi = d_g_f2 + (size_t)row * G3_;
        const float* gh = d_gh_f + (size_t)row * G3_;
        float h  = d_f1[idx];
        float r = sigm(gi[j]       + bih_f[j]       + gh[j]       + bhh_f[j]);
        float z = sigm(gi[Hh_+j]   + bih_f[Hh_+j]   + gh[Hh_+j]   + bhh_f[Hh_+j]);
        float n = tanhf(gi[2*Hh_+j] + bih_f[2*Hh_+j] + r * (gh[2*Hh_+j] + bhh_f[2*Hh_+j]));
        float f2 = (1.f - z) * n + z * h;
        d_db[(size_t)row*H_ + j] = 0.5f * (h + f2);
    }
    {
        const float* gi = d_g_b2 + (size_t)row * G3_;
        const float* gh = d_gh_b + (size_t)row * G3_;
        float h  = d_b1[idx];
        float r = sigm(gi[j]       + bih_b[j]       + gh[j]       + bhh_b[j]);
        float z = sigm(gi[Hh_+j]   + bih_b[Hh_+j]   + gh[Hh_+j]   + bhh_b[Hh_+j]);
        float n = tanhf(gi[2*Hh_+j] + bih_b[2*Hh_+j] + r * (gh[2*Hh_+j] + bhh_b[2*Hh_+j]));
        float b2 = (1.f - z) * n + z * h;
        d_db[(size_t)row*H_ + Hh_ + j] = 0.5f * (h + b2);
    }
}

// ---------------- attention ----------------
__global__ void logits_kernel(const float* __restrict__ key, const int* __restrict__ attn_mask)
{
    int t = blockIdx.y;
    int warp = threadIdx.x >> 5, lane = threadIdx.x & 31;
    int u = blockIdx.x * 8 + warp;
    const float* kv = key + (size_t)t * H_;
    const float* d  = d_db + ((size_t)t*U_ + u) * H_;
    float acc = 0.f;
    for (int h = lane; h < H_; h += 32) acc += kv[h] * d[h];
    #pragma unroll
    for (int s = 16; s > 0; s >>= 1) acc += __shfl_xor_sync(0xFFFFFFFFu, acc, s);
    if (lane == 0)
        d_logits[t*U_ + u] = attn_mask[t*U_ + u] ? acc : -1e9f;
}

__global__ void softmax_kernel()
{
    int t = blockIdx.x;
    __shared__ float red[256];
    int tid = threadIdx.x;
    float mx = -INFINITY;
    for (int u = tid; u < U_; u += 256) mx = fmaxf(mx, d_logits[t*U_+u]);
    red[tid] = mx; __syncthreads();
    for (int s = 128; s > 0; s >>= 1) { if (tid < s) red[tid] = fmaxf(red[tid], red[tid+s]); __syncthreads(); }
    mx = red[0]; __syncthreads();
    float sum = 0.f;
    for (int u = tid; u < U_; u += 256) sum += expf(d_logits[t*U_+u] - mx);
    red[tid] = sum; __syncthreads();
    for (int s = 128; s > 0; s >>= 1) { if (tid < s) red[tid] += red[tid+s]; __syncthreads(); }
    sum = red[0];
    float inv = 1.f / sum;
    for (int u = tid; u < U_; u += 256) d_wsm[t*U_+u] = expf(d_logits[t*U_+u] - mx) * inv;
}

__global__ void attn_kernel()
{
    int t = blockIdx.x;
    int h = threadIdx.x;                 // 512 threads
    __shared__ float ws[U_];
    for (int u = h; u < U_; u += H_) ws[u] = d_wsm[t*U_+u];
    __syncthreads();
    float acc = 0.f;
    const float* d = d_db + (size_t)t*U_*H_ + h;
    for (int u = 0; u < U_; u++) acc += ws[u] * d[(size_t)u*H_];
    d_attnv[t*H_ + h] = acc;
}

__global__ void add_attn_kernel(const float* __restrict__ final_feature)
{
    int idx = blockIdx.x * blockDim.x + threadIdx.x;   // T_*L_*H_
    int h = idx & (H_-1);
    int t = idx >> 15;
    d_ffin[idx] = final_feature[idx] + d_attnv[t*H_ + h];
}

// ---------------- final log-softmax ----------------
__global__ void logsoftmax_kernel(float* __restrict__ out)
{
    int r = blockIdx.x;
    int tid = threadIdx.x;
    __shared__ float red[256];
    const float* x = d_probs + (size_t)r * OUTC_;
    float mx = -INFINITY;
    for (int c = tid; c < OUTC_; c += 256) mx = fmaxf(mx, x[c]);
    red[tid] = mx; __syncthreads();
    for (int s = 128; s > 0; s >>= 1) { if (tid < s) red[tid] = fmaxf(red[tid], red[tid+s]); __syncthreads(); }
    mx = red[0]; __syncthreads();
    float sum = 0.f;
    for (int c = tid; c < OUTC_; c += 256) sum += expf(x[c] - mx);
    red[tid] = sum; __syncthreads();
    for (int s = 128; s > 0; s >>= 1) { if (tid < s) red[tid] += red[tid+s]; __syncthreads(); }
    float lse = mx + logf(red[0]);
    for (int c = tid; c < OUTC_; c += 256) out[(size_t)r*OUTC_ + c] = x[c] - lse;
}

// ---------------- host launcher ----------------
#define SYM(p, t, s) do { void* _t; cudaGetSymbolAddress(&_t, s); (p) = (t*)_t; } while (0)

extern "C" void kernel_launch(void* const* d_in, const int* in_sizes, int n_in,
                              void* d_out, int out_size)
{
    const float* feat          = (const float*)d_in[0];
    const float* key           = (const float*)d_in[1];
    const float* final_feature = (const float*)d_in[2];
    const float* Wih_f         = (const float*)d_in[3];
    const float* Whh_f         = (const float*)d_in[4];
    const float* bih_f         = (const float*)d_in[5];
    const float* bhh_f         = (const float*)d_in[6];
    const float* Wih_b         = (const float*)d_in[7];
    const float* Whh_b         = (const float*)d_in[8];
    const float* bih_b         = (const float*)d_in[9];
    const float* bhh_b         = (const float*)d_in[10];
    const float* Wb            = (const float*)d_in[11];
    const float* bb            = (const float*)d_in[12];
    const float* Kemb          = (const float*)d_in[13];
    const int*   col_idx       = (const int*)d_in[14];
    const int*   col_mask      = (const int*)d_in[15];
    const int*   tab_idx       = (const int*)d_in[16];
    const int*   tab_mask      = (const int*)d_in[17];
    const int*   attn_mask     = (const int*)d_in[18];
    float* out = (float*)d_out;

    float *Pf, *Pb, *gh_f, *gh_b, *db, *ffin, *ff, *probs;
    __nv_bfloat16 *featS, *WihfS, *WihbS, *WhhfS, *WhhbS, *f1S, *b1S;
    SYM(Pf, float, d_Pf);   SYM(Pb, float, d_Pb);
    SYM(gh_f, float, d_gh_f); SYM(gh_b, float, d_gh_b);
    SYM(db, float, d_db);   SYM(ffin, float, d_ffin); SYM(ff, float, d_ff); SYM(probs, float, d_probs);
    SYM(featS, __nv_bfloat16, d_featS);
    SYM(WihfS, __nv_bfloat16, d_WihfS); SYM(WihbS, __nv_bfloat16, d_WihbS);
    SYM(WhhfS, __nv_bfloat16, d_WhhfS); SYM(WhhbS, __nv_bfloat16, d_WhhbS);
    SYM(f1S, __nv_bfloat16, d_f1S);     SYM(b1S, __nv_bfloat16, d_b1S);

    // 0) split-bf16 conversions
    split_bf16_kernel<<<(TDB_*H_+255)/256, 256>>>(feat,  featS, TDB_*H_, H_, 0);
    split_bf16_kernel<<<(G3_*H_+255)/256, 256>>>(Wih_f, WihfS, G3_*H_, H_, 1);
    split_bf16_kernel<<<(G3_*H_+255)/256, 256>>>(Wih_b, WihbS, G3_*H_, H_, 1);
    split_bf16_kernel<<<(G3_*Hh_+255)/256, 256>>>(Whh_f, WhhfS, G3_*Hh_, Hh_, 1);
    split_bf16_kernel<<<(G3_*Hh_+255)/256, 256>>>(Whh_b, WhhbS, G3_*Hh_, Hh_, 1);

    // 1) projection GEMMs on tensor cores (HMMA): P = feat @ Wih^T  (8192 x 768, K'=1536)
    {
        dim3 grid(G3_/128, TDB_/128);
        gemm_wmma<<<grid, 256>>>(featS, WihfS, Pf, TDB_, G3_, 3*H_, G3_);
        gemm_wmma<<<grid, 256>>>(featS, WihbS, Pb, TDB_, G3_, 3*H_, G3_);
    }

    // 2) masked means in projected space -> gi buffers
    proj_gather_kernel<<<dim3(U_, T_), 192>>>(col_idx, col_mask, tab_idx, tab_mask);

    // 3) first GRU steps (h = 0), emits f1/b1 fp32 + split-bf16
    gru_first_kernel<<<TU_*Hh_/256, 256>>>(bih_f, bhh_f, bih_b, bhh_b);

    // 4) hidden-projection GEMMs on tensor cores: (16384 x 768, K'=768) — raw, bhh added later
    {
        dim3 grid(G3_/128, TU_/128);
        gemm_wmma<<<grid, 256>>>(f1S, WhhfS, gh_f, TU_, G3_, 3*Hh_, G3_);
        gemm_wmma<<<grid, 256>>>(b1S, WhhbS, gh_b, TU_, G3_, 3*Hh_, G3_);
    }

    // 5) second GRU steps + db_emb (adds bih + bhh)
    gru_second_kernel<<<TU_*Hh_/256, 256>>>(bih_f, bhh_f, bih_b, bhh_b);

    // 6) attention
    logits_kernel<<<dim3(U_/8, T_), 256>>>(key, attn_mask);
    softmax_kernel<<<T_, 256>>>();
    attn_kernel<<<T_, H_>>>();

    // 7) feature + attn, then ff = tanh(ffin @ Wb^T + bb)
    add_attn_kernel<<<T_*L_*H_/256, 256>>>(final_feature);
    {
        dim3 grid(H_/128, T_*L_/128, 1);
        sgemm_nt<128,128,16,8,8><<<grid, 256>>>(ffin, Wb, bb, ff, T_*L_, H_, H_, H_, H_, H_, 0,0,0, 1);
    }

    // 8) db_prob: per-t (64 x 1024) = ff[t] (64x512) @ db_emb[t] (1024x512)^T
    {
        dim3 grid(U_/128, L_/64, T_);
        sgemm_nt<64,128,16,4,8><<<grid, 256>>>(ff, db, nullptr, probs,
            L_, U_, H_, H_, H_, OUTC_,
            (long long)L_*H_, (long long)U_*H_, (long long)L_*OUTC_, 0);
    }
    // 9) kw_prob: (1024 x 64) = ff @ Kemb^T, at column offset U_
    {
        dim3 grid(K_/64, T_*L_/64, 1);
        sgemm_nt<64,64,16,4,4><<<grid, 256>>>(ff, Kemb, nullptr, probs + U_,
            T_*L_, K_, H_, H_, H_, OUTC_, 0,0,0, 0);
    }

    // 10) log-softmax over last dim (1088) -> output
    logsoftmax_kernel<<<T_*L_, 256>>>(out);
}